// round 2
// baseline (speedup 1.0000x reference)
#include <cuda_runtime.h>

// GaussianHistogram: hist[b,i,j] = sum_n exp(-0.5*((x1-ci)/s)^2) * exp(-0.5*((x2-cj)/s)^2) * mask
// With SIGMA = DELTA/sqrt(2pi): exponent for bin-offset k is exactly -pi*(u-k)^2,
// and COEF == 1.0 exactly. Gaussian support is ~±4.5 bins at fp32 granularity
// (exp(-pi*4.5^2) ~ 2e-28), so each sample is a separable 9x9 stamp scattered
// with global f32 reductions into the 2MB (L2-resident) output.

#define GH_BINS   256
#define GH_LOGN   15          // N = 32768 per batch
#define GH_W      4           // stamp radius
#define GH_WW     (2*GH_W+1)  // 9

__global__ void __launch_bounds__(256)
GaussianHistogram_55542517072143_kernel(const float* __restrict__ x1,
                                        const float* __restrict__ x2,
                                        const float* __restrict__ mask,
                                        float* __restrict__ out,
                                        int total)
{
    int idx = blockIdx.x * blockDim.x + threadIdx.x;
    if (idx >= total) return;

    int b = idx >> GH_LOGN;           // batch index (N = 32768)

    float a1 = x1[idx];
    float a2 = x2[idx];
    float m  = mask[idx];

    // s = (x - MIN_V)/DELTA ; MIN_V = -0.25, DELTA = 1.5/256
    const float INV_DELTA = 256.0f / 1.5f;
    float s1 = (a1 + 0.25f) * INV_DELTA;
    float s2 = (a2 + 0.25f) * INV_DELTA;

    int i1 = (int)floorf(s1);
    int i2 = (int)floorf(s2);
    // x in [0,1) => i in [42,213]; clamp is pure OOB insurance.
    i1 = min(max(i1, GH_W), GH_BINS - 1 - GH_W);
    i2 = min(max(i2, GH_W), GH_BINS - 1 - GH_W);

    float u1 = s1 - 0.5f - (float)i1;  // in [-0.5, 0.5)
    float u2 = s2 - 0.5f - (float)i2;

    const float NPI = -3.14159265358979f;

    float w1[GH_WW], w2[GH_WW];
#pragma unroll
    for (int k = 0; k < GH_WW; k++) {
        float d = u1 - (float)(k - GH_W);
        w1[k] = __expf(NPI * d * d);
    }
#pragma unroll
    for (int k = 0; k < GH_WW; k++) {
        float d = u2 - (float)(k - GH_W);
        w2[k] = __expf(NPI * d * d) * m;   // mask folded into the x2 factor
    }

    float* base = out + ((size_t)b << 16)          // b * 256*256
                      + (size_t)(i1 - GH_W) * GH_BINS
                      + (i2 - GH_W);

#pragma unroll
    for (int di = 0; di < GH_WW; di++) {
        float a = w1[di];
        float* row = base + di * GH_BINS;
#pragma unroll
        for (int dj = 0; dj < GH_WW; dj++) {
            atomicAdd(row + dj, a * w2[dj]);       // emitted as RED.E.ADD.F32 (no return)
        }
    }
}

extern "C" void kernel_launch(void* const* d_in, const int* in_sizes, int n_in,
                              void* d_out, int out_size)
{
    const float* x1   = (const float*)d_in[0];
    const float* x2   = (const float*)d_in[1];
    const float* mask = (const float*)d_in[2];
    float* out = (float*)d_out;

    // d_out is poisoned with 0xAA — zero it first (memset node is graph-capturable).
    cudaMemsetAsync(d_out, 0, (size_t)out_size * sizeof(float));

    int total = in_sizes[0];               // B*N = 262144
    int threads = 256;
    int blocks = (total + threads - 1) / threads;
    GaussianHistogram_55542517072143_kernel<<<blocks, threads>>>(x1, x2, mask, out, total);
}

// round 3
// speedup vs baseline: 6.2133x; 6.2133x over previous
#include <cuda_runtime.h>

// GaussianHistogram: hist[b,i,j] = sum_n exp(-0.5*((x1-ci)/s)^2) * exp(-0.5*((x2-cj)/s)^2) * mask
// SIGMA = DELTA/sqrt(2pi)  =>  exponent for bin-offset d is exactly -pi*d^2, COEF == 1.0.
// Gaussian truncated at radius 2 (exp(-pi*2.5^2) ~ 3e-9 — adds ~5e-6 rel err, 100x under gate).
// Each sample scatters a separable 5x8 stamp (8 cols = v4-aligned window covering the 5
// needed cols) via red.global.add.v4.f32 into the 2MB L2-resident output.

#define GH_BINS   256
#define GH_LOGN   15          // N = 32768 per batch
#define GH_W      2           // stamp radius
#define GH_ROWS   (2*GH_W+1)  // 5

__global__ void __launch_bounds__(256)
GaussianHistogram_55542517072143_kernel(const float* __restrict__ x1,
                                        const float* __restrict__ x2,
                                        const float* __restrict__ mask,
                                        float* __restrict__ out,
                                        int total)
{
    int idx = blockIdx.x * blockDim.x + threadIdx.x;
    if (idx >= total) return;

    int b = idx >> GH_LOGN;           // batch index (N = 32768)

    float a1 = x1[idx];
    float a2 = x2[idx];
    float m  = mask[idx];

    // continuous bin coordinate: f = (x - MIN_V)/DELTA - 0.5 ; center c_i is at f == i
    const float INV_DELTA = 256.0f / 1.5f;
    float f1 = (a1 + 0.25f) * INV_DELTA - 0.5f;
    float f2 = (a2 + 0.25f) * INV_DELTA - 0.5f;

    int i1 = (int)floorf(f1 + 0.5f);  // nearest bin
    int i2 = (int)floorf(f2 + 0.5f);
    // x in [0,1) => i in [42,213]; clamps are pure OOB insurance.
    i1 = min(max(i1, GH_W), GH_BINS - 1 - GH_W);
    i2 = min(max(i2, GH_W), GH_BINS - 6);          // window j0..j0+7 must fit

    int j0 = (i2 - GH_W) & ~3;        // 16B-aligned column window start; covers i2-2..i2+2

    const float NPI = -3.14159265358979f;

    // row weights (x1 direction), 5 taps
    float w1[GH_ROWS];
#pragma unroll
    for (int k = 0; k < GH_ROWS; k++) {
        float d = f1 - (float)(i1 - GH_W + k);
        w1[k] = __expf(NPI * d * d);
    }

    // column weights over the aligned 8-wide window, mask folded in
    float v = f2 - (float)j0;
    float w2[8];
#pragma unroll
    for (int t = 0; t < 8; t++) {
        float d = v - (float)t;
        w2[t] = __expf(NPI * d * d) * m;   // taps outside i2+-2 are ~0 and harmless
    }

    float* base = out + ((size_t)b << 16)            // b * 256*256
                      + (size_t)(i1 - GH_W) * GH_BINS
                      + j0;

#pragma unroll
    for (int di = 0; di < GH_ROWS; di++) {
        float a = w1[di];
        float* row = base + di * GH_BINS;
        float p0 = a * w2[0], p1 = a * w2[1], p2 = a * w2[2], p3 = a * w2[3];
        float p4 = a * w2[4], p5 = a * w2[5], p6 = a * w2[6], p7 = a * w2[7];
        asm volatile("red.global.add.v4.f32 [%0], {%1,%2,%3,%4};"
                     :: "l"(row),     "f"(p0), "f"(p1), "f"(p2), "f"(p3) : "memory");
        asm volatile("red.global.add.v4.f32 [%0], {%1,%2,%3,%4};"
                     :: "l"(row + 4), "f"(p4), "f"(p5), "f"(p6), "f"(p7) : "memory");
    }
}

extern "C" void kernel_launch(void* const* d_in, const int* in_sizes, int n_in,
                              void* d_out, int out_size)
{
    const float* x1   = (const float*)d_in[0];
    const float* x2   = (const float*)d_in[1];
    const float* mask = (const float*)d_in[2];
    float* out = (float*)d_out;

    // d_out is poisoned with 0xAA — zero it first (memset node is graph-capturable).
    cudaMemsetAsync(d_out, 0, (size_t)out_size * sizeof(float));

    int total = in_sizes[0];               // B*N = 262144
    int threads = 256;
    int blocks = (total + threads - 1) / threads;
    GaussianHistogram_55542517072143_kernel<<<blocks, threads>>>(x1, x2, mask, out, total);
}